// round 7
// baseline (speedup 1.0000x reference)
#include <cuda_runtime.h>

#define B_ 256
#define T_ 512
#define C_ 256
#define L_ 64
#define S_ 129      // 2L+1 extended states
#define PR 68       // compressed pg row: [eb, pad, pad, pad, p1, p3, ..., p127]

// Scratch (allocation-free rule: __device__ globals). ~35.7 MB (L2-resident).
__device__ float g_pg[(size_t)B_ * T_ * PR + 64];
__device__ float g_loss[B_];

// ---------------------------------------------------------------------------
// Kernel 1: warp-per-(b,t)-row softmax + gather, compressed output.
// Even (blank) states all share eb, stored once per row; odd state p_{2j+1}
// at row[4+j]. Traffic: 134 MB read + 36 MB write.
// ---------------------------------------------------------------------------
__global__ void __launch_bounds__(256) probs_kernel(
    const float* __restrict__ logits, const int* __restrict__ targets) {
  int warp = threadIdx.x >> 5, lane = threadIdx.x & 31;
  size_t row = (size_t)blockIdx.x * 8 + warp;   // row = b*T + t
  int b = (int)(row >> 9);                      // T_ = 512

  __shared__ float sh[8][C_];

  const float4* lrow = (const float4*)(logits + row * C_);
  float4 v0 = lrow[lane];        // c = 4*lane
  float4 v1 = lrow[lane + 32];   // c = 128 + 4*lane
  float4 e0, e1;
  e0.x = __expf(v0.x); e0.y = __expf(v0.y); e0.z = __expf(v0.z); e0.w = __expf(v0.w);
  e1.x = __expf(v1.x); e1.y = __expf(v1.y); e1.z = __expf(v1.z); e1.w = __expf(v1.w);

  float s = ((e0.x + e0.y) + (e0.z + e0.w)) + ((e1.x + e1.y) + (e1.z + e1.w));
  #pragma unroll
  for (int o = 16; o; o >>= 1) s += __shfl_xor_sync(0xffffffffu, s, o);
  float inv = __frcp_rn(s);

  ((float4*)sh[warp])[lane]      = e0;
  ((float4*)sh[warp])[lane + 32] = e1;
  __syncwarp();

  // lane l -> labels 2l, 2l+1 (ext states 4l+1, 4l+3)
  int2 tv = ((const int2*)(targets + b * L_))[lane];
  float2 o;
  o.x = sh[warp][tv.x] * inv;
  o.y = sh[warp][tv.y] * inv;

  float* orow = g_pg + row * PR;
  ((float2*)(orow + 4))[lane] = o;
  if (lane == 0) orow[0] = sh[warp][0] * inv;   // eb
}

// ---------------------------------------------------------------------------
// Kernel 2: linear-domain CTC forward, one warp per batch row.
// Lane l owns states s = 4l..4l+3; lane 31 also carries s = 128 (blank).
// ONE shfl_up per step. Validity masking (s < Sb = 2*tl+1) restored after the
// R6 underflow bug: odd-state masks folded into the prefetch loads (free),
// blank-state masks applied as 3 mults/step, so invalid alphas stay exactly 0
// and the renorm max tracks only live states. 16-deep statically-indexed
// register prefetch (pg ~36 MB, mostly L2-resident).
// ---------------------------------------------------------------------------
__global__ void __launch_bounds__(32) alpha_kernel(
    const int* __restrict__ targets,
    const int* __restrict__ input_lengths,
    const int* __restrict__ target_lengths) {
  int b = blockIdx.x;
  int lane = threadIdx.x;
  int len = input_lengths[b];
  int tl = target_lengths[b];
  int Sb = 2 * tl + 1;

  const float* __restrict__ pgb = g_pg + (size_t)b * T_ * PR;
  const int* __restrict__ tg = targets + b * L_;

  // skip masks: s=4l+1 (label 2l): skip iff l>=1 && tg[2l]!=tg[2l-1]
  //             s=4l+3 (label 2l+1): skip iff tg[2l+1]!=tg[2l]
  int t0 = tg[2 * lane], t1 = tg[2 * lane + 1];
  float skip1 = 0.f, skip3 = (t1 != t0) ? 1.f : 0.f;
  if (lane > 0) skip1 = (t0 != tg[2 * lane - 1]) ? 1.f : 0.f;

  // validity masks (state < Sb)
  float m0 = (4 * lane + 0 < Sb) ? 1.f : 0.f;
  float m1 = (4 * lane + 1 < Sb) ? 1.f : 0.f;
  float m2 = (4 * lane + 2 < Sb) ? 1.f : 0.f;
  float m3 = (4 * lane + 3 < Sb) ? 1.f : 0.f;
  float m4 = (lane == 31 && Sb > 128) ? 1.f : 0.f;   // state 128

  // t = 0: alpha[0] = eb(row0), alpha[1] = p1(row0)
  float a0 = 0.f, a1 = 0.f, a2 = 0.f, a3 = 0.f, a4 = 0.f;
  if (lane == 0) { a0 = pgb[0]; a1 = pgb[4]; }

  // 16-deep prefetch (rows t..t+15); odd-state masks folded into the load
  float  ebv[16];
  float2 plv[16];
  #pragma unroll
  for (int u = 0; u < 16; u++) {
    const float* prow = pgb + (size_t)(1 + u) * PR;
    ebv[u] = __ldg(prow);
    float2 pl = __ldg((const float2*)(prow + 4) + lane);
    pl.x *= m1; pl.y *= m3;
    plv[u] = pl;
  }

  int e_total = 0;
  int nsteps = len - 1;            // len in [412, 512]
  int nblk = nsteps >> 4;
  int t = 1;

#define CTC_STEP(EB, PL)                                                  \
  do {                                                                    \
    float u1 = __shfl_up_sync(0xffffffffu, a3, 1);                        \
    u1 = lane ? u1 : 0.f;                                                 \
    float n0 = (a0 + u1) * (EB);                                          \
    float n1 = fmaf(skip1, u1, a1 + a0) * (PL).x;                         \
    float n2 = (a2 + a1) * (EB);                                          \
    float n3 = fmaf(skip3, a1, a3 + a2) * (PL).y;                         \
    float n4 = (a4 + a3) * (EB);  /* s=128 on lane 31 */                  \
    a0 = n0 * m0; a1 = n1; a2 = n2 * m2; a3 = n3; a4 = n4 * m4;           \
  } while (0)

#define CTC_RENORM()                                                      \
  do {                                                                    \
    float lm = fmaxf(fmaxf(a0, a1), fmaxf(fmaxf(a2, a3), a4));            \
    unsigned mb = __reduce_max_sync(0xffffffffu, __float_as_uint(lm));    \
    int e = (int)(mb >> 23) - 127;                                        \
    if (mb != 0u && e != 0) {                                             \
      float f = __int_as_float((127 - e) << 23);  /* 2^(-e) */            \
      a0 *= f; a1 *= f; a2 *= f; a3 *= f; a4 *= f;                        \
      e_total += e;                                                       \
    }                                                                     \
  } while (0)

  for (int blk = 0; blk < nblk; blk++) {
    #pragma unroll
    for (int u = 0; u < 16; u++) {
      float  EB = ebv[u];
      float2 PL = plv[u];
      int tp = t + u + 16;
      if (tp < T_) {
        const float* prow = pgb + (size_t)tp * PR;
        ebv[u] = __ldg(prow);
        float2 pl = __ldg((const float2*)(prow + 4) + lane);
        pl.x *= m1; pl.y *= m3;
        plv[u] = pl;
      }
      CTC_STEP(EB, PL);
      if ((u & 3) == 3) CTC_RENORM();
    }
    t += 16;
  }

  // remainder (<= 15 steps): rows t..t+14 already resident in ebv/plv
  {
    int rem = len - t;
    #pragma unroll
    for (int u = 0; u < 16; u++) {
      if (u < rem) {
        CTC_STEP(ebv[u], plv[u]);
        if ((u & 3) == 3) CTC_RENORM();
      }
    }
  }

  // gather alpha[2tl], alpha[2tl-1]
  __shared__ float shf[132];
  shf[4 * lane + 0] = a0;
  shf[4 * lane + 1] = a1;
  shf[4 * lane + 2] = a2;
  shf[4 * lane + 3] = a3;
  if (lane == 31) shf[128] = a4;
  __syncwarp();
  if (lane == 0) {
    float ssum = shf[2 * tl] + shf[2 * tl - 1];
    float loss = -(logf(ssum) + (float)e_total * 0.69314718055994530942f);
    if (!isfinite(loss) || loss > 1e20f) loss = 0.f;   // zero_infinity
    g_loss[b] = loss / (float)tl;
  }
#undef CTC_STEP
#undef CTC_RENORM
}

// ---------------------------------------------------------------------------
// Kernel 3: deterministic mean over batch.
// ---------------------------------------------------------------------------
__global__ void __launch_bounds__(256) finalize_kernel(float* __restrict__ out) {
  int i = threadIdx.x;
  float v = g_loss[i];
  #pragma unroll
  for (int o = 16; o; o >>= 1) v += __shfl_xor_sync(0xffffffffu, v, o);
  __shared__ float ws[8];
  if ((i & 31) == 0) ws[i >> 5] = v;
  __syncthreads();
  if (i == 0) {
    float s = 0.f;
    #pragma unroll
    for (int w = 0; w < 8; w++) s += ws[w];
    out[0] = s * (1.0f / (float)B_);
  }
}

extern "C" void kernel_launch(void* const* d_in, const int* in_sizes, int n_in,
                              void* d_out, int out_size) {
  const float* logits         = (const float*)d_in[0];
  const int*   targets        = (const int*)d_in[1];
  const int*   input_lengths  = (const int*)d_in[2];
  const int*   target_lengths = (const int*)d_in[3];
  (void)in_sizes; (void)n_in; (void)out_size;

  probs_kernel<<<(B_ * T_) / 8, 256>>>(logits, targets);
  alpha_kernel<<<B_, 32>>>(targets, input_lengths, target_lengths);
  finalize_kernel<<<1, 256>>>((float*)d_out);
}

// round 8
// speedup vs baseline: 1.0831x; 1.0831x over previous
#include <cuda_runtime.h>

#define B_ 256
#define T_ 512
#define C_ 256
#define L_ 64
#define S_ 129      // 2L+1 extended states
#define PR 68       // compressed pg row: [eb, pad, pad, pad, p1, p3, ..., p127]

// Scratch (allocation-free rule: __device__ globals). ~35.7 MB (L2-resident).
__device__ float g_pg[(size_t)B_ * T_ * PR + 64];
__device__ float g_loss[B_];

// ---------------------------------------------------------------------------
// Kernel 1: warp-per-(b,t)-row softmax + gather, compressed output.
// At the memory roofline (134 MB read + 36 MB write) — unchanged.
// ---------------------------------------------------------------------------
__global__ void __launch_bounds__(256) probs_kernel(
    const float* __restrict__ logits, const int* __restrict__ targets) {
  int warp = threadIdx.x >> 5, lane = threadIdx.x & 31;
  size_t row = (size_t)blockIdx.x * 8 + warp;   // row = b*T + t
  int b = (int)(row >> 9);                      // T_ = 512

  __shared__ float sh[8][C_];

  const float4* lrow = (const float4*)(logits + row * C_);
  float4 v0 = lrow[lane];        // c = 4*lane
  float4 v1 = lrow[lane + 32];   // c = 128 + 4*lane
  float4 e0, e1;
  e0.x = __expf(v0.x); e0.y = __expf(v0.y); e0.z = __expf(v0.z); e0.w = __expf(v0.w);
  e1.x = __expf(v1.x); e1.y = __expf(v1.y); e1.z = __expf(v1.z); e1.w = __expf(v1.w);

  float s = ((e0.x + e0.y) + (e0.z + e0.w)) + ((e1.x + e1.y) + (e1.z + e1.w));
  #pragma unroll
  for (int o = 16; o; o >>= 1) s += __shfl_xor_sync(0xffffffffu, s, o);
  float inv = __frcp_rn(s);

  ((float4*)sh[warp])[lane]      = e0;
  ((float4*)sh[warp])[lane + 32] = e1;
  __syncwarp();

  // lane l -> labels 2l, 2l+1 (ext states 4l+1, 4l+3)
  int2 tv = ((const int2*)(targets + b * L_))[lane];
  float2 o;
  o.x = sh[warp][tv.x] * inv;
  o.y = sh[warp][tv.y] * inv;

  float* orow = g_pg + row * PR;
  ((float2*)(orow + 4))[lane] = o;
  if (lane == 0) orow[0] = sh[warp][0] * inv;   // eb
}

// ---------------------------------------------------------------------------
// Kernel 2: linear-domain CTC forward, one warp per batch row.
// Lane l owns states s = 4l..4l+3; lane 31 also carries s = 128.
// R8: renorm off the critical path. Probabilities are pre-scaled by 2^8 at
// refill (typical per-step decay ~2^-8, exact -8*(len-1)*ln2 correction at the
// end). Corrective power-of-2 renorm every 4 steps is PIPELINED: apply the
// factor computed 4 steps ago (1 FMUL on path), then launch fmax+REDUX whose
// result is consumed at the next boundary. Branchless. Validity masking
// reduced to a single mul on the shuffled value (zeroes propagate elsewhere;
// odd-state masks folded into loads).
// ---------------------------------------------------------------------------
__global__ void __launch_bounds__(32) alpha_kernel(
    const int* __restrict__ targets,
    const int* __restrict__ input_lengths,
    const int* __restrict__ target_lengths) {
  int b = blockIdx.x;
  int lane = threadIdx.x;
  int len = input_lengths[b];
  int tl = target_lengths[b];
  int Sb = 2 * tl + 1;

  const float* __restrict__ pgb = g_pg + (size_t)b * T_ * PR;
  const int* __restrict__ tg = targets + b * L_;

  // skip masks: s=4l+1 (label 2l): skip iff l>=1 && tg[2l]!=tg[2l-1]
  //             s=4l+3 (label 2l+1): skip iff tg[2l+1]!=tg[2l]
  int t0 = tg[2 * lane], t1 = tg[2 * lane + 1];
  float skip1 = 0.f, skip3 = (t1 != t0) ? 1.f : 0.f;
  if (lane > 0) skip1 = (t0 != tg[2 * lane - 1]) ? 1.f : 0.f;

  // validity constants (scale 2^8 folded into the odd-state masks)
  float c0 = (lane > 0 && 4 * lane < Sb) ? 1.f : 0.f;        // gates shuffled a3
  float c1 = (4 * lane + 1 < Sb) ? 256.f : 0.f;              // odd state 4l+1
  float c3 = (4 * lane + 3 < Sb) ? 256.f : 0.f;              // odd state 4l+3

  // t = 0: alpha[0] = eb(row0), alpha[1] = p1(row0)  (unscaled)
  float a0 = 0.f, a1 = 0.f, a2 = 0.f, a3 = 0.f, a4 = 0.f;
  if (lane == 0) { a0 = pgb[0]; a1 = pgb[4]; }

  // 16-deep prefetch (rows t..t+15); masks+scale folded into the loads
  float  ebv[16];
  float2 plv[16];
  #pragma unroll
  for (int u = 0; u < 16; u++) {
    const float* prow = pgb + (size_t)(1 + u) * PR;
    ebv[u] = __ldg(prow) * 256.f;
    float2 pl = __ldg((const float2*)(prow + 4) + lane);
    pl.x *= c1; pl.y *= c3;
    plv[u] = pl;
  }

  int e_total = 0;
  float fpend = 1.f;
  int epend = 0;
  int nsteps = len - 1;            // len in [412, 512]
  int nblk = nsteps >> 4;
  int t = 1;

#define CTC_STEP(EB, PL)                                                  \
  do {                                                                    \
    float u1 = __shfl_up_sync(0xffffffffu, a3, 1) * c0;                   \
    float n0 = (a0 + u1) * (EB);                                          \
    float n1 = fmaf(skip1, u1, a1 + a0) * (PL).x;                         \
    float n2 = (a2 + a1) * (EB);                                          \
    float n3 = fmaf(skip3, a1, a3 + a2) * (PL).y;                         \
    float n4 = (a4 + a3) * (EB);  /* s=128 on lane 31 */                  \
    a0 = n0; a1 = n1; a2 = n2; a3 = n3; a4 = n4;                          \
  } while (0)

  // Apply the correction computed 4 steps ago, then start the next one.
  // All rescales are exact powers of two; e_total is bumped exactly when
  // the multiply is applied, so the final log stays exact.
#define CTC_RENORM_PIPE()                                                 \
  do {                                                                    \
    a0 *= fpend; a1 *= fpend; a2 *= fpend; a3 *= fpend; a4 *= fpend;      \
    e_total += epend;                                                     \
    float lm = fmaxf(fmaxf(a0, a1), fmaxf(fmaxf(a2, a3), a4));            \
    unsigned mb = __reduce_max_sync(0xffffffffu, __float_as_uint(lm));    \
    epend = (mb != 0u) ? ((int)(mb >> 23) - 127) : 0;                     \
    fpend = __int_as_float((127 - epend) << 23);  /* 2^(-epend) */        \
  } while (0)

  for (int blk = 0; blk < nblk; blk++) {
    #pragma unroll
    for (int u = 0; u < 16; u++) {
      float  EB = ebv[u];
      float2 PL = plv[u];
      int tp = t + u + 16;
      if (tp < T_) {
        const float* prow = pgb + (size_t)tp * PR;
        ebv[u] = __ldg(prow) * 256.f;
        float2 pl = __ldg((const float2*)(prow + 4) + lane);
        pl.x *= c1; pl.y *= c3;
        plv[u] = pl;
      }
      CTC_STEP(EB, PL);
      if ((u & 3) == 3) CTC_RENORM_PIPE();
    }
    t += 16;
  }

  // remainder (<= 15 steps): rows t..t+14 already resident in ebv/plv
  {
    int rem = len - t;
    #pragma unroll
    for (int u = 0; u < 16; u++) {
      if (u < rem) CTC_STEP(ebv[u], plv[u]);
    }
  }

  // gather alpha[2tl], alpha[2tl-1]
  __shared__ float shf[132];
  shf[4 * lane + 0] = a0;
  shf[4 * lane + 1] = a1;
  shf[4 * lane + 2] = a2;
  shf[4 * lane + 3] = a3;
  if (lane == 31) shf[128] = a4;
  __syncwarp();
  if (lane == 0) {
    float ssum = shf[2 * tl] + shf[2 * tl - 1];
    // a_true = a_stored * 2^(e_total - 8*(len-1))
    float loss = -(logf(ssum) +
                   (float)(e_total - 8 * (len - 1)) * 0.69314718055994530942f);
    if (!isfinite(loss) || loss > 1e20f) loss = 0.f;   // zero_infinity
    g_loss[b] = loss / (float)tl;
  }
#undef CTC_STEP
#undef CTC_RENORM_PIPE
}

// ---------------------------------------------------------------------------
// Kernel 3: deterministic mean over batch.
// ---------------------------------------------------------------------------
__global__ void __launch_bounds__(256) finalize_kernel(float* __restrict__ out) {
  int i = threadIdx.x;
  float v = g_loss[i];
  #pragma unroll
  for (int o = 16; o; o >>= 1) v += __shfl_xor_sync(0xffffffffu, v, o);
  __shared__ float ws[8];
  if ((i & 31) == 0) ws[i >> 5] = v;
  __syncthreads();
  if (i == 0) {
    float s = 0.f;
    #pragma unroll
    for (int w = 0; w < 8; w++) s += ws[w];
    out[0] = s * (1.0f / (float)B_);
  }
}

extern "C" void kernel_launch(void* const* d_in, const int* in_sizes, int n_in,
                              void* d_out, int out_size) {
  const float* logits         = (const float*)d_in[0];
  const int*   targets        = (const int*)d_in[1];
  const int*   input_lengths  = (const int*)d_in[2];
  const int*   target_lengths = (const int*)d_in[3];
  (void)in_sizes; (void)n_in; (void)out_size;

  probs_kernel<<<(B_ * T_) / 8, 256>>>(logits, targets);
  alpha_kernel<<<B_, 32>>>(targets, input_lengths, target_lengths);
  finalize_kernel<<<1, 256>>>((float*)d_out);
}

// round 10
// speedup vs baseline: 2.0555x; 1.8977x over previous
#include <cuda_runtime.h>

#define B_ 256
#define T_ 512
#define C_ 256
#define L_ 64

__device__ float g_loss[B_];

// ---------------------------------------------------------------------------
// Fused CTC kernel: one block per batch row. 9 warps:
//   warps 0-7 (producers): each phase, warp w computes softmax of logits row
//     (phase+1)*8+w and writes the compressed prob row [eb*256 | p_odd*c*256]
//     into the smem ring slot; its global loads are issued one phase ahead.
//   warp 8 (consumer): runs the linear-domain CTC recurrence (R8 scheme:
//     4 states/lane + state 128 on lane 31, 1 shfl/step, probs pre-scaled by
//     2^8, pipelined power-of-2 renorm every 4 steps) straight out of smem.
// Ring: 2 phases x 8 rows. __syncthreads() once per phase.
// ---------------------------------------------------------------------------
__global__ void __launch_bounds__(288) ctc_fused_kernel(
    const float* __restrict__ logits,
    const int* __restrict__ targets,
    const int* __restrict__ input_lengths,
    const int* __restrict__ target_lengths) {
  __shared__ float ring[2][8][68];     // [eb, pad,pad,pad, p1,p3,...,p127]
  __shared__ float scratch[8][256];    // per-producer-warp exp scratch
  __shared__ int   stg[L_];
  __shared__ float shf[132];

  int b = blockIdx.x;
  int tid = threadIdx.x;
  int wid = tid >> 5, lane = tid & 31;
  int len = input_lengths[b];
  int tl  = target_lengths[b];
  int Sb  = 2 * tl + 1;

  if (tid < L_) stg[tid] = targets[b * L_ + tid];
  __syncthreads();                                    // barrier 1

  const float* lg = logits + (size_t)b * T_ * C_;

  if (wid < 8) {
    // ---------------- producers ----------------
    int t0l = stg[2 * lane], t1l = stg[2 * lane + 1];
    float c1 = (4 * lane + 1 < Sb) ? 256.f : 0.f;
    float c3 = (4 * lane + 3 < Sb) ? 256.f : 0.f;
    float* scr = scratch[wid];

#define PRODUCE(A0, A1, SLOT)                                              \
    do {                                                                   \
      float4 eA, eB;                                                       \
      eA.x = __expf((A0).x); eA.y = __expf((A0).y);                        \
      eA.z = __expf((A0).z); eA.w = __expf((A0).w);                        \
      eB.x = __expf((A1).x); eB.y = __expf((A1).y);                        \
      eB.z = __expf((A1).z); eB.w = __expf((A1).w);                        \
      float s = ((eA.x + eA.y) + (eA.z + eA.w)) +                          \
                ((eB.x + eB.y) + (eB.z + eB.w));                           \
      _Pragma("unroll")                                                    \
      for (int o = 16; o; o >>= 1) s += __shfl_xor_sync(0xffffffffu, s, o);\
      float inv = __frcp_rn(s);                                            \
      ((float4*)scr)[lane]      = eA;                                      \
      ((float4*)scr)[lane + 32] = eB;                                      \
      __syncwarp();                                                        \
      float2 o2;                                                           \
      o2.x = scr[t0l] * inv * c1;                                          \
      o2.y = scr[t1l] * inv * c3;                                          \
      ((float2*)((SLOT) + 4))[lane] = o2;                                  \
      if (lane == 0) (SLOT)[0] = scr[0] * inv * 256.f;                     \
      __syncwarp();                                                        \
    } while (0)

    // preamble: produce row wid into ring[0]; preload row 8+wid
    float4 rbA, rbB;
    {
      const float4* pr = (const float4*)(lg + (size_t)wid * C_);
      float4 aA = pr[lane], aB = pr[lane + 32];
      const float4* pn = (const float4*)(lg + (size_t)(8 + wid) * C_);
      rbA = pn[lane]; rbB = pn[lane + 32];
      PRODUCE(aA, aB, ring[0][wid]);
    }
    __syncthreads();                                  // barrier 2

    for (int p = 0; p < 63; p++) {
      // issue loads for row (p+2)*8+wid (clamped), then produce (p+1)*8+wid
      int rowl = (p + 2) * 8 + wid;
      rowl = rowl < T_ ? rowl : T_ - 1;
      const float4* pn = (const float4*)(lg + (size_t)rowl * C_);
      float4 nA = pn[lane], nB = pn[lane + 32];
      PRODUCE(rbA, rbB, ring[(p + 1) & 1][wid]);
      rbA = nA; rbB = nB;
      __syncthreads();
    }
#undef PRODUCE
  } else {
    // ---------------- consumer (warp 8) ----------------
    int t0l = stg[2 * lane], t1l = stg[2 * lane + 1];
    float skip1 = 0.f, skip3 = (t1l != t0l) ? 1.f : 0.f;
    if (lane > 0) skip1 = (t0l != stg[2 * lane - 1]) ? 1.f : 0.f;
    float c0 = (lane > 0 && 4 * lane < Sb) ? 1.f : 0.f;

    float a0 = 0.f, a1 = 0.f, a2 = 0.f, a3 = 0.f, a4 = 0.f;
    int e_total = 0, epend = 0;
    float fpend = 1.f;

#define CTC_STEP(EB, PL)                                                   \
    do {                                                                   \
      float u1 = __shfl_up_sync(0xffffffffu, a3, 1) * c0;                  \
      float n0 = (a0 + u1) * (EB);                                         \
      float n1 = fmaf(skip1, u1, a1 + a0) * (PL).x;                        \
      float n2 = (a2 + a1) * (EB);                                         \
      float n3 = fmaf(skip3, a1, a3 + a2) * (PL).y;                        \
      float n4 = (a4 + a3) * (EB);                                         \
      a0 = n0; a1 = n1; a2 = n2; a3 = n3; a4 = n4;                         \
    } while (0)

#define CTC_RENORM_PIPE()                                                  \
    do {                                                                   \
      a0 *= fpend; a1 *= fpend; a2 *= fpend; a3 *= fpend; a4 *= fpend;     \
      e_total += epend;                                                    \
      float lm = fmaxf(fmaxf(a0, a1), fmaxf(fmaxf(a2, a3), a4));           \
      unsigned mb = __reduce_max_sync(0xffffffffu, __float_as_uint(lm));   \
      epend = (mb != 0u) ? ((int)(mb >> 23) - 127) : 0;                    \
      fpend = __int_as_float((127 - epend) << 23);                         \
    } while (0)

#define CTC_PHASE(P)                                                       \
    do {                                                                   \
      float(*buf)[68] = ring[(P) & 1];                                     \
      float  ebv[8];                                                       \
      float2 plv[8];                                                       \
      _Pragma("unroll")                                                    \
      for (int u = 0; u < 8; u++) {                                        \
        ebv[u] = buf[u][0];                                                \
        plv[u] = ((float2*)(buf[u] + 4))[lane];                            \
      }                                                                    \
      _Pragma("unroll")                                                    \
      for (int u = 0; u < 8; u++) {                                        \
        int tt = (P) * 8 + u;                                              \
        if (tt == 0) {                                                     \
          if (lane == 0) {                                                 \
            a0 = ebv[0] * (1.f / 256.f);                                   \
            a1 = plv[0].x * (1.f / 256.f);                                 \
          }                                                                \
        } else if (tt < len) {                                             \
          CTC_STEP(ebv[u], plv[u]);                                        \
          if ((tt & 3) == 3) CTC_RENORM_PIPE();                            \
        }                                                                  \
      }                                                                    \
    } while (0)

    __syncthreads();                                  // barrier 2 (ring0 ready)
    for (int p = 0; p < 63; p++) {
      CTC_PHASE(p);
      __syncthreads();
    }
    CTC_PHASE(63);

    // final gather
    shf[4 * lane + 0] = a0;
    shf[4 * lane + 1] = a1;
    shf[4 * lane + 2] = a2;
    shf[4 * lane + 3] = a3;
    if (lane == 31) shf[128] = a4;
    __syncwarp();
    if (lane == 0) {
      float ssum = shf[2 * tl] + shf[2 * tl - 1];
      // a_true = a_stored * 2^(e_total - 8*(len-1))
      float loss = -(logf(ssum) +
                     (float)(e_total - 8 * (len - 1)) * 0.69314718055994530942f);
      if (!isfinite(loss) || loss > 1e20f) loss = 0.f;   // zero_infinity
      g_loss[b] = loss / (float)tl;
    }
#undef CTC_STEP
#undef CTC_RENORM_PIPE
#undef CTC_PHASE
  }
}

// ---------------------------------------------------------------------------
// Finalize: deterministic mean over batch.
// ---------------------------------------------------------------------------
__global__ void __launch_bounds__(256) finalize_kernel(float* __restrict__ out) {
  int i = threadIdx.x;
  float v = g_loss[i];
  #pragma unroll
  for (int o = 16; o; o >>= 1) v += __shfl_xor_sync(0xffffffffu, v, o);
  __shared__ float ws[8];
  if ((i & 31) == 0) ws[i >> 5] = v;
  __syncthreads();
  if (i == 0) {
    float s = 0.f;
    #pragma unroll
    for (int w = 0; w < 8; w++) s += ws[w];
    out[0] = s * (1.0f / (float)B_);
  }
}

extern "C" void kernel_launch(void* const* d_in, const int* in_sizes, int n_in,
                              void* d_out, int out_size) {
  const float* logits         = (const float*)d_in[0];
  const int*   targets        = (const int*)d_in[1];
  const int*   input_lengths  = (const int*)d_in[2];
  const int*   target_lengths = (const int*)d_in[3];
  (void)in_sizes; (void)n_in; (void)out_size;

  ctc_fused_kernel<<<B_, 288>>>(logits, targets, input_lengths, target_lengths);
  finalize_kernel<<<1, 256>>>((float*)d_out);
}